// round 2
// baseline (speedup 1.0000x reference)
#include <cuda_runtime.h>
#include <cstdint>

#define BB 128
#define LL 512
#define DD 768
#define HH 8
#define RR 32

#define KC 16
#define NCHUNK (DD / KC)      // 48
#define FSTRIDE 20            // padded floats per staged feat row (conflict-free LDS.128)

typedef unsigned long long u64;

__device__ __forceinline__ u64 ffma2(u64 a, u64 b, u64 c) {
    u64 d;
    asm("fma.rn.f32x2 %0, %1, %2, %3;" : "=l"(d) : "l"(a), "l"(b), "l"(c));
    return d;
}
__device__ __forceinline__ float f2sum(u64 a) {
    float lo, hi;
    asm("mov.b64 {%0, %1}, %2;" : "=f"(lo), "=f"(hi) : "l"(a));
    return lo + hi;
}

// scratch: concatenated pooled outputs [b][head 768 | tail 768]
__device__ float g_cat[BB * 2 * DD];

__global__ __launch_bounds__(256, 2)
void k_pool(const float* __restrict__ head_value,
            const float* __restrict__ tail_value,
            const float* __restrict__ prop_embed,
            const float* __restrict__ W_att,
            const float* __restrict__ b_att,
            const int*   __restrict__ head_ids,
            const int*   __restrict__ tail_ids,
            const int*   __restrict__ rc_ids,
            float*       __restrict__ out)
{
    extern __shared__ float smem[];
    float* feat_s  = smem;                          // 512*20 = 10240 f (40 KB)
    float* Wc_s    = feat_s + LL * FSTRIDE;         // 8*16   = 128 f
    float* logit_s = Wc_s + HH * KC;                // 8*512  = 4096 f
    float* attn_s  = logit_s + HH * LL;             // 512 f
    float* inv_s   = attn_s + LL;                   // 8 f
    int*   ids_s   = (int*)(inv_s + 8);             // 512 i  (premultiplied row offsets)

    const int tid = threadIdx.x;
    const int bid = blockIdx.x;
    const int b   = bid >> 1;
    const int br  = bid & 1;
    const int rc  = rc_ids[b];

    const int*   ids = (br ? tail_ids : head_ids) + b * LL;
    const float* val = (br ? tail_value : head_value) + (size_t)b * LL * DD;

    for (int i = tid; i < LL; i += 256) ids_s[i] = ids[i] * DD;
    __syncthreads();

    const int lq = tid & 127;   // l-group: l = lq + 128*j
    const int kh = tid >> 7;    // k-half within chunk

    // f32x2 accumulators: .lo = even-k partial, .hi = odd-k partial
    u64 acc[HH][4];
    #pragma unroll
    for (int h = 0; h < HH; h++)
        #pragma unroll
        for (int j = 0; j < 4; j++) acc[h][j] = 0ull;

    const int grow[8] = { (tid+0*256)>>2, (tid+1*256)>>2, (tid+2*256)>>2, (tid+3*256)>>2,
                          (tid+4*256)>>2, (tid+5*256)>>2, (tid+6*256)>>2, (tid+7*256)>>2 };
    const int gf4 = (tid & 3) * 4;

    // ---- prologue: prefetch chunk 0 into registers
    float4 rv[8];
    float4 wv;
    #pragma unroll
    for (int j = 0; j < 8; j++)
        rv[j] = *(const float4*)(prop_embed + ids_s[grow[j]] + gf4);
    if (tid < 32)
        wv = *(const float4*)(W_att + ((size_t)(tid >> 2) * RR + rc) * DD + (tid & 3) * 4);

    #pragma unroll 1
    for (int c = 0; c < NCHUNK; c++) {
        // ---- commit staged registers to smem
        #pragma unroll
        for (int j = 0; j < 8; j++)
            *(float4*)(feat_s + grow[j] * FSTRIDE + gf4) = rv[j];
        if (tid < 32)
            *(float4*)(Wc_s + (tid >> 2) * KC + (tid & 3) * 4) = wv;
        __syncthreads();

        // ---- prefetch chunk c+1 (scoreboard drains under the FMA below)
        if (c + 1 < NCHUNK) {
            const int k0 = (c + 1) * KC;
            #pragma unroll
            for (int j = 0; j < 8; j++)
                rv[j] = *(const float4*)(prop_embed + ids_s[grow[j]] + k0 + gf4);
            if (tid < 32)
                wv = *(const float4*)(W_att + ((size_t)(tid >> 2) * RR + rc) * DD + k0 + (tid & 3) * 4);
        }

        // ---- register-tiled contraction, packed f32x2 along k
        #pragma unroll
        for (int k4 = 0; k4 < 2; k4++) {
            const int kk = kh * 8 + k4 * 4;
            const ulonglong2 F0 = *(const ulonglong2*)(feat_s + (lq      ) * FSTRIDE + kk);
            const ulonglong2 F1 = *(const ulonglong2*)(feat_s + (lq + 128) * FSTRIDE + kk);
            const ulonglong2 F2 = *(const ulonglong2*)(feat_s + (lq + 256) * FSTRIDE + kk);
            const ulonglong2 F3 = *(const ulonglong2*)(feat_s + (lq + 384) * FSTRIDE + kk);
            #pragma unroll
            for (int h = 0; h < HH; h++) {
                const ulonglong2 W = *(const ulonglong2*)(Wc_s + h * KC + kk);  // broadcast
                acc[h][0] = ffma2(F0.x, W.x, acc[h][0]);
                acc[h][1] = ffma2(F1.x, W.x, acc[h][1]);
                acc[h][2] = ffma2(F2.x, W.x, acc[h][2]);
                acc[h][3] = ffma2(F3.x, W.x, acc[h][3]);
                acc[h][0] = ffma2(F0.y, W.y, acc[h][0]);
                acc[h][1] = ffma2(F1.y, W.y, acc[h][1]);
                acc[h][2] = ffma2(F2.y, W.y, acc[h][2]);
                acc[h][3] = ffma2(F3.y, W.y, acc[h][3]);
            }
        }
        __syncthreads();
    }

    // ---- split-k reduction (kh=1 partials via smem, aliasing feat_s)
    if (kh) {
        #pragma unroll
        for (int h = 0; h < HH; h++)
            #pragma unroll
            for (int j = 0; j < 4; j++)
                feat_s[lq * 32 + h * 4 + j] = f2sum(acc[h][j]);
    }
    __syncthreads();
    if (!kh) {
        #pragma unroll
        for (int h = 0; h < HH; h++) {
            const float bs = b_att[h * RR + rc];
            #pragma unroll
            for (int j = 0; j < 4; j++) {
                float x = f2sum(acc[h][j]) + feat_s[lq * 32 + h * 4 + j] + bs;
                logit_s[h * LL + lq + 128 * j] = fmaxf(x, 0.f);
            }
        }
    }
    __syncthreads();

    // ---- softmax per head: warp w owns head w
    {
        const int wid  = tid >> 5;
        const int lane = tid & 31;
        const int h = wid;
        float x[16];
        float m = 0.f;
        #pragma unroll
        for (int i = 0; i < 16; i++) {
            x[i] = logit_s[h * LL + lane + 32 * i];
            m = fmaxf(m, x[i]);
        }
        #pragma unroll
        for (int off = 16; off > 0; off >>= 1)
            m = fmaxf(m, __shfl_xor_sync(0xffffffffu, m, off));
        float s = 0.f;
        #pragma unroll
        for (int i = 0; i < 16; i++) {
            const float e = __expf(x[i] - m);
            logit_s[h * LL + lane + 32 * i] = e;
            s += e;
        }
        #pragma unroll
        for (int off = 16; off > 0; off >>= 1)
            s += __shfl_xor_sync(0xffffffffu, s, off);
        if (lane == 0) inv_s[h] = 1.f / s;
    }
    __syncthreads();

    // ---- attn_mean = mean over heads; write output + keep in smem for pooling
    for (int l = tid; l < LL; l += 256) {
        float s = 0.f;
        #pragma unroll
        for (int h = 0; h < HH; h++)
            s += logit_s[h * LL + l] * inv_s[h];
        s *= (1.0f / HH);
        attn_s[l] = s;
        out[129 + br * (BB * LL) + b * LL + l] = s;
    }
    __syncthreads();

    // ---- weighted value pooling: pooled[b,d] = sum_l attn_mean[l] * value[l,d]
    float a0 = 0.f, a1 = 0.f, a2 = 0.f;
    for (int l = 0; l < LL; l += 4) {
        const float am0 = attn_s[l + 0];
        const float am1 = attn_s[l + 1];
        const float am2 = attn_s[l + 2];
        const float am3 = attn_s[l + 3];
        const float* r0 = val + (size_t)(l + 0) * DD;
        const float* r1 = val + (size_t)(l + 1) * DD;
        const float* r2 = val + (size_t)(l + 2) * DD;
        const float* r3 = val + (size_t)(l + 3) * DD;
        a0 += am0 * __ldcs(r0 + tid)       + am1 * __ldcs(r1 + tid)
            + am2 * __ldcs(r2 + tid)       + am3 * __ldcs(r3 + tid);
        a1 += am0 * __ldcs(r0 + tid + 256) + am1 * __ldcs(r1 + tid + 256)
            + am2 * __ldcs(r2 + tid + 256) + am3 * __ldcs(r3 + tid + 256);
        a2 += am0 * __ldcs(r0 + tid + 512) + am1 * __ldcs(r1 + tid + 512)
            + am2 * __ldcs(r2 + tid + 512) + am3 * __ldcs(r3 + tid + 512);
    }
    float* dst = g_cat + (size_t)b * (2 * DD) + br * DD;
    dst[tid]       = a0;
    dst[tid + 256] = a1;
    dst[tid + 512] = a2;
}

__global__ void k_score(const float* __restrict__ W1,
                        const float* __restrict__ b1,
                        const int*   __restrict__ rc_ids,
                        float*       __restrict__ out)
{
    __shared__ float sc[BB];
    __shared__ float mg[BB / 2];
    const int tid  = threadIdx.x;
    const int wid  = tid >> 5;
    const int lane = tid & 31;

    for (int b = wid; b < BB; b += 8) {
        const int rc = rc_ids[b];
        const float* cat = g_cat + (size_t)b * (2 * DD);
        const float* w   = W1 + (size_t)rc * (2 * DD);
        float s = 0.f;
        for (int d = lane; d < 2 * DD; d += 32)
            s += cat[d] * w[d];
        #pragma unroll
        for (int off = 16; off > 0; off >>= 1)
            s += __shfl_xor_sync(0xffffffffu, s, off);
        if (lane == 0) {
            s += b1[rc];
            sc[b] = s;
            out[b] = s;
        }
    }
    __syncthreads();
    if (tid < BB / 2)
        mg[tid] = fmaxf(1.0f - (sc[tid] - sc[tid + BB / 2]), 0.f);
    __syncthreads();
    if (tid == 0) {
        float s = 0.f;
        for (int i = 0; i < BB / 2; i++) s += mg[i];
        out[BB] = s * (1.0f / (BB / 2));
    }
}

extern "C" void kernel_launch(void* const* d_in, const int* in_sizes, int n_in,
                              void* d_out, int out_size)
{
    const float* head_value = (const float*)d_in[0];
    const float* tail_value = (const float*)d_in[1];
    const float* prop_embed = (const float*)d_in[2];
    const float* W_att      = (const float*)d_in[3];
    const float* b_att      = (const float*)d_in[4];
    const float* W1         = (const float*)d_in[5];
    const float* b1         = (const float*)d_in[6];
    const int*   head_ids   = (const int*)d_in[7];
    const int*   tail_ids   = (const int*)d_in[8];
    const int*   rc_ids     = (const int*)d_in[9];
    float* out = (float*)d_out;

    const int smem_bytes = (LL * FSTRIDE + HH * KC + HH * LL + LL + 8 + LL) * 4;
    cudaFuncSetAttribute(k_pool, cudaFuncAttributeMaxDynamicSharedMemorySize, smem_bytes);

    k_pool<<<2 * BB, 256, smem_bytes>>>(head_value, tail_value, prop_embed,
                                        W_att, b_att, head_ids, tail_ids, rc_ids, out);
    k_score<<<1, 256>>>(W1, b1, rc_ids, out);
}

// round 3
// speedup vs baseline: 1.2644x; 1.2644x over previous
#include <cuda_runtime.h>
#include <cstdint>

#define BB 128
#define LL 512
#define DD 768
#define HH 8
#define RR 32

#define KC 16
#define NCHUNK (DD / KC)      // 48
#define FSTRIDE 20            // padded floats per staged feat row (conflict-free LDS.128)

typedef unsigned long long u64;

__device__ __forceinline__ u64 ffma2(u64 a, u64 b, u64 c) {
    u64 d;
    asm("fma.rn.f32x2 %0, %1, %2, %3;" : "=l"(d) : "l"(a), "l"(b), "l"(c));
    return d;
}
__device__ __forceinline__ float f2sum(u64 a) {
    float lo, hi;
    asm("mov.b64 {%0, %1}, %2;" : "=f"(lo), "=f"(hi) : "l"(a));
    return lo + hi;
}

// scratch: concatenated pooled outputs [b][head 768 | tail 768]
__device__ float g_cat[BB * 2 * DD];

__global__ __launch_bounds__(256, 2)
void k_pool(const float* __restrict__ head_value,
            const float* __restrict__ tail_value,
            const float* __restrict__ prop_embed,
            const float* __restrict__ W_att,
            const float* __restrict__ b_att,
            const int*   __restrict__ head_ids,
            const int*   __restrict__ tail_ids,
            const int*   __restrict__ rc_ids,
            float*       __restrict__ out)
{
    extern __shared__ float smem[];
    float* feat_s  = smem;                          // 512*20 = 10240 f (40 KB)
    float* Wc_s    = feat_s + LL * FSTRIDE;         // 8*16   = 128 f
    float* logit_s = Wc_s + HH * KC;                // 8*512  = 4096 f
    float* attn_s  = logit_s + HH * LL;             // 512 f
    float* inv_s   = attn_s + LL;                   // 8 f
    int*   ids_s   = (int*)(inv_s + 8);             // 512 i  (premultiplied row offsets)

    const int tid = threadIdx.x;
    const int bid = blockIdx.x;
    const int b   = bid >> 1;
    const int br  = bid & 1;
    const int rc  = rc_ids[b];

    const int*   ids = (br ? tail_ids : head_ids) + b * LL;
    const float* val = (br ? tail_value : head_value) + (size_t)b * LL * DD;

    for (int i = tid; i < LL; i += 256) ids_s[i] = ids[i] * DD;
    __syncthreads();

    const int lq = tid & 127;   // l-group: l = lq + 128*j
    const int kh = tid >> 7;    // k-half within chunk

    // f32x2 accumulators: .lo = even-k partial, .hi = odd-k partial
    u64 acc[HH][4];
    #pragma unroll
    for (int h = 0; h < HH; h++)
        #pragma unroll
        for (int j = 0; j < 4; j++) acc[h][j] = 0ull;

    const int grow[8] = { (tid+0*256)>>2, (tid+1*256)>>2, (tid+2*256)>>2, (tid+3*256)>>2,
                          (tid+4*256)>>2, (tid+5*256)>>2, (tid+6*256)>>2, (tid+7*256)>>2 };
    const int gf4 = (tid & 3) * 4;

    // ---- prologue: prefetch chunk 0 into registers
    float4 rv[8];
    float4 wv;
    #pragma unroll
    for (int j = 0; j < 8; j++)
        rv[j] = *(const float4*)(prop_embed + ids_s[grow[j]] + gf4);
    if (tid < 32)
        wv = *(const float4*)(W_att + ((size_t)(tid >> 2) * RR + rc) * DD + (tid & 3) * 4);

    #pragma unroll 1
    for (int c = 0; c < NCHUNK; c++) {
        // ---- commit staged registers to smem
        #pragma unroll
        for (int j = 0; j < 8; j++)
            *(float4*)(feat_s + grow[j] * FSTRIDE + gf4) = rv[j];
        if (tid < 32)
            *(float4*)(Wc_s + (tid >> 2) * KC + (tid & 3) * 4) = wv;
        __syncthreads();

        // ---- prefetch chunk c+1 (scoreboard drains under the FMA below)
        if (c + 1 < NCHUNK) {
            const int k0 = (c + 1) * KC;
            #pragma unroll
            for (int j = 0; j < 8; j++)
                rv[j] = *(const float4*)(prop_embed + ids_s[grow[j]] + k0 + gf4);
            if (tid < 32)
                wv = *(const float4*)(W_att + ((size_t)(tid >> 2) * RR + rc) * DD + k0 + (tid & 3) * 4);
        }

        // ---- register-tiled contraction, packed f32x2 along k
        #pragma unroll
        for (int k4 = 0; k4 < 2; k4++) {
            const int kk = kh * 8 + k4 * 4;
            const ulonglong2 F0 = *(const ulonglong2*)(feat_s + (lq      ) * FSTRIDE + kk);
            const ulonglong2 F1 = *(const ulonglong2*)(feat_s + (lq + 128) * FSTRIDE + kk);
            const ulonglong2 F2 = *(const ulonglong2*)(feat_s + (lq + 256) * FSTRIDE + kk);
            const ulonglong2 F3 = *(const ulonglong2*)(feat_s + (lq + 384) * FSTRIDE + kk);
            #pragma unroll
            for (int h = 0; h < HH; h++) {
                const ulonglong2 W = *(const ulonglong2*)(Wc_s + h * KC + kk);  // broadcast
                acc[h][0] = ffma2(F0.x, W.x, acc[h][0]);
                acc[h][1] = ffma2(F1.x, W.x, acc[h][1]);
                acc[h][2] = ffma2(F2.x, W.x, acc[h][2]);
                acc[h][3] = ffma2(F3.x, W.x, acc[h][3]);
                acc[h][0] = ffma2(F0.y, W.y, acc[h][0]);
                acc[h][1] = ffma2(F1.y, W.y, acc[h][1]);
                acc[h][2] = ffma2(F2.y, W.y, acc[h][2]);
                acc[h][3] = ffma2(F3.y, W.y, acc[h][3]);
            }
        }
        __syncthreads();
    }

    // ---- split-k reduction (kh=1 partials via smem, aliasing feat_s)
    if (kh) {
        #pragma unroll
        for (int h = 0; h < HH; h++)
            #pragma unroll
            for (int j = 0; j < 4; j++)
                feat_s[lq * 32 + h * 4 + j] = f2sum(acc[h][j]);
    }
    __syncthreads();
    if (!kh) {
        #pragma unroll
        for (int h = 0; h < HH; h++) {
            const float bs = b_att[h * RR + rc];
            #pragma unroll
            for (int j = 0; j < 4; j++) {
                float x = f2sum(acc[h][j]) + feat_s[lq * 32 + h * 4 + j] + bs;
                logit_s[h * LL + lq + 128 * j] = fmaxf(x, 0.f);
            }
        }
    }
    __syncthreads();

    // ---- softmax per head: warp w owns head w
    {
        const int wid  = tid >> 5;
        const int lane = tid & 31;
        const int h = wid;
        float x[16];
        float m = 0.f;
        #pragma unroll
        for (int i = 0; i < 16; i++) {
            x[i] = logit_s[h * LL + lane + 32 * i];
            m = fmaxf(m, x[i]);
        }
        #pragma unroll
        for (int off = 16; off > 0; off >>= 1)
            m = fmaxf(m, __shfl_xor_sync(0xffffffffu, m, off));
        float s = 0.f;
        #pragma unroll
        for (int i = 0; i < 16; i++) {
            const float e = __expf(x[i] - m);
            logit_s[h * LL + lane + 32 * i] = e;
            s += e;
        }
        #pragma unroll
        for (int off = 16; off > 0; off >>= 1)
            s += __shfl_xor_sync(0xffffffffu, s, off);
        if (lane == 0) inv_s[h] = 1.f / s;
    }
    __syncthreads();

    // ---- attn_mean = mean over heads; write output + keep in smem for pooling
    for (int l = tid; l < LL; l += 256) {
        float s = 0.f;
        #pragma unroll
        for (int h = 0; h < HH; h++)
            s += logit_s[h * LL + l] * inv_s[h];
        s *= (1.0f / HH);
        attn_s[l] = s;
        out[129 + br * (BB * LL) + b * LL + l] = s;
    }
    __syncthreads();

    // ---- weighted value pooling: pooled[b,d] = sum_l attn_mean[l] * value[l,d]
    float a0 = 0.f, a1 = 0.f, a2 = 0.f;
    for (int l = 0; l < LL; l += 4) {
        const float am0 = attn_s[l + 0];
        const float am1 = attn_s[l + 1];
        const float am2 = attn_s[l + 2];
        const float am3 = attn_s[l + 3];
        const float* r0 = val + (size_t)(l + 0) * DD;
        const float* r1 = val + (size_t)(l + 1) * DD;
        const float* r2 = val + (size_t)(l + 2) * DD;
        const float* r3 = val + (size_t)(l + 3) * DD;
        a0 += am0 * __ldcs(r0 + tid)       + am1 * __ldcs(r1 + tid)
            + am2 * __ldcs(r2 + tid)       + am3 * __ldcs(r3 + tid);
        a1 += am0 * __ldcs(r0 + tid + 256) + am1 * __ldcs(r1 + tid + 256)
            + am2 * __ldcs(r2 + tid + 256) + am3 * __ldcs(r3 + tid + 256);
        a2 += am0 * __ldcs(r0 + tid + 512) + am1 * __ldcs(r1 + tid + 512)
            + am2 * __ldcs(r2 + tid + 512) + am3 * __ldcs(r3 + tid + 512);
    }
    float* dst = g_cat + (size_t)b * (2 * DD) + br * DD;
    dst[tid]       = a0;
    dst[tid + 256] = a1;
    dst[tid + 512] = a2;
}

// one block per b: score[b] = dot(cat[b], W1[rc_b]) + b1[rc_b]
__global__ __launch_bounds__(256)
void k_score(const float* __restrict__ W1,
             const float* __restrict__ b1,
             const int*   __restrict__ rc_ids,
             float*       __restrict__ out)
{
    __shared__ float red[8];
    const int b    = blockIdx.x;
    const int tid  = threadIdx.x;
    const int lane = tid & 31;
    const int wid  = tid >> 5;
    const int rc   = rc_ids[b];

    const float* cat = g_cat + (size_t)b * (2 * DD);
    const float* w   = W1 + (size_t)rc * (2 * DD);

    // 1536 floats = 384 float4; 256 threads: thread handles f4 indices tid and tid+256(<384)
    float s;
    {
        const float4 c0 = *(const float4*)(cat + tid * 4);
        const float4 w0 = *(const float4*)(w   + tid * 4);
        s = c0.x*w0.x + c0.y*w0.y + c0.z*w0.z + c0.w*w0.w;
        if (tid < 128) {
            const float4 c1 = *(const float4*)(cat + (tid + 256) * 4);
            const float4 w1 = *(const float4*)(w   + (tid + 256) * 4);
            s += c1.x*w1.x + c1.y*w1.y + c1.z*w1.z + c1.w*w1.w;
        }
    }
    #pragma unroll
    for (int off = 16; off > 0; off >>= 1)
        s += __shfl_xor_sync(0xffffffffu, s, off);
    if (lane == 0) red[wid] = s;
    __syncthreads();
    if (tid == 0) {
        float t = red[0];
        #pragma unroll
        for (int i = 1; i < 8; i++) t += red[i];
        out[b] = t + b1[rc];
    }
}

__global__ void k_loss(float* __restrict__ out)
{
    const int lane = threadIdx.x;   // 32 threads
    float s = 0.f;
    #pragma unroll
    for (int i = 0; i < 2; i++) {
        const int p = lane + 32 * i;
        s += fmaxf(1.0f - (out[p] - out[p + BB / 2]), 0.f);
    }
    #pragma unroll
    for (int off = 16; off > 0; off >>= 1)
        s += __shfl_xor_sync(0xffffffffu, s, off);
    if (lane == 0) out[BB] = s * (1.0f / (BB / 2));
}

extern "C" void kernel_launch(void* const* d_in, const int* in_sizes, int n_in,
                              void* d_out, int out_size)
{
    const float* head_value = (const float*)d_in[0];
    const float* tail_value = (const float*)d_in[1];
    const float* prop_embed = (const float*)d_in[2];
    const float* W_att      = (const float*)d_in[3];
    const float* b_att      = (const float*)d_in[4];
    const float* W1         = (const float*)d_in[5];
    const float* b1         = (const float*)d_in[6];
    const int*   head_ids   = (const int*)d_in[7];
    const int*   tail_ids   = (const int*)d_in[8];
    const int*   rc_ids     = (const int*)d_in[9];
    float* out = (float*)d_out;

    const int smem_bytes = (LL * FSTRIDE + HH * KC + HH * LL + LL + 8 + LL) * 4;
    cudaFuncSetAttribute(k_pool, cudaFuncAttributeMaxDynamicSharedMemorySize, smem_bytes);

    k_pool<<<2 * BB, 256, smem_bytes>>>(head_value, tail_value, prop_embed,
                                        W_att, b_att, head_ids, tail_ids, rc_ids, out);
    k_score<<<BB, 256>>>(W1, b1, rc_ids, out);
    k_loss<<<1, 32>>>(out);
}

// round 5
// speedup vs baseline: 1.8449x; 1.4591x over previous
#include <cuda_runtime.h>
#include <cstdint>

#define BB 128
#define LL 512
#define DD 768
#define HH 8
#define RR 32

#define KC 16
#define NCH (DD / KC)         // 48 chunks
#define FS 20                 // padded floats per staged feat row (conflict-free LDS.128)

// smem float offsets
#define F0_OFF 0
#define F1_OFF (LL * FS)                  // 10240
#define WB_OFF (2 * LL * FS)              // 20480, 2 x 8 x 16 floats
#define IDS_OFF (WB_OFF + 2 * HH * KC)    // 20736, 512 ints
#define SMEM_FLOATS (IDS_OFF + LL)        // 21248 -> 85 KB

typedef unsigned long long u64;

__device__ __forceinline__ u64 ffma2(u64 a, u64 b, u64 c) {
    u64 d;
    asm("fma.rn.f32x2 %0, %1, %2, %3;" : "=l"(d) : "l"(a), "l"(b), "l"(c));
    return d;
}
__device__ __forceinline__ float f2sum(u64 a) {
    float lo, hi;
    asm("mov.b64 {%0, %1}, %2;" : "=f"(lo), "=f"(hi) : "l"(a));
    return lo + hi;
}
__device__ __forceinline__ void cpa16(uint32_t dst, const float* src) {
    asm volatile("cp.async.cg.shared.global [%0], [%1], 16;\n" :: "r"(dst), "l"(src));
}
__device__ __forceinline__ void cpa_commit() {
    asm volatile("cp.async.commit_group;\n");
}
__device__ __forceinline__ void cpa_wait1() {
    asm volatile("cp.async.wait_group 1;\n");
}

// scratch: concatenated pooled outputs [b][head 768 | tail 768]
__device__ float g_cat[BB * 2 * DD];

__global__ __launch_bounds__(256, 2)
void k_pool(const float* __restrict__ head_value,
            const float* __restrict__ tail_value,
            const float* __restrict__ prop_embed,
            const float* __restrict__ W_att,
            const float* __restrict__ b_att,
            const int*   __restrict__ head_ids,
            const int*   __restrict__ tail_ids,
            const int*   __restrict__ rc_ids,
            float*       __restrict__ out)
{
    extern __shared__ float smem[];
    float* feat[2] = { smem + F0_OFF, smem + F1_OFF };
    float* Wb      = smem + WB_OFF;           // [2][8][16]
    int*   ids_s   = (int*)(smem + IDS_OFF);
    float* logit_s = smem + F0_OFF;           // alias (8*512 f), used post-loop
    float* attn_s  = smem + F1_OFF;           // alias (512 f)
    float* inv_s   = smem + F1_OFF + LL;      // alias (8 f)
    float* red     = smem + F0_OFF;           // alias (4*768 f), used after softmax

    const uint32_t smem_u32 = (uint32_t)__cvta_generic_to_shared(smem);

    const int tid = threadIdx.x;
    const int bid = blockIdx.x;
    const int b   = bid >> 1;
    const int br  = bid & 1;
    const int rc  = rc_ids[b];

    const int*   ids = (br ? tail_ids : head_ids) + b * LL;
    const float* val = (br ? tail_value : head_value) + (size_t)b * LL * DD;

    for (int i = tid; i < LL; i += 256) ids_s[i] = ids[i] * DD;
    __syncthreads();

    // ---- per-thread gather plan: 8 ops/chunk, fixed rows, fixed quarter
    const int q   = tid & 3;            // 16B quarter within 64B row-chunk
    const int r0  = tid >> 2;           // base row
    int rowoff[8];                      // element offset of each owned row
    uint32_t dsto[8];                   // smem byte offset within a feat buffer
    #pragma unroll
    for (int j = 0; j < 8; j++) {
        const int r = r0 + 64 * j;
        rowoff[j] = ids_s[r] + q * 4;
        dsto[j]   = (uint32_t)((r * FS + q * 4) * 4);
    }
    const int wsrc = ((tid >> 2) * RR + rc) * DD + q * 4;      // for tid<32
    const uint32_t wdst = (uint32_t)((WB_OFF + (tid >> 2) * KC + q * 4) * 4);

    // ---- prologue: issue chunks 0 and 1
    #pragma unroll
    for (int p = 0; p < 2; p++) {
        const int k0 = p * KC;
        const uint32_t fb = smem_u32 + (uint32_t)((p ? F1_OFF : F0_OFF) * 4);
        #pragma unroll
        for (int j = 0; j < 8; j++)
            cpa16(fb + dsto[j], prop_embed + rowoff[j] + k0);
        if (tid < 32)
            cpa16(smem_u32 + wdst + (uint32_t)(p * HH * KC * 4), W_att + wsrc + k0);
        cpa_commit();
    }

    // f32x2 accumulators: acc[h][j], j -> l = tid + 256*j ; .lo even-k, .hi odd-k
    u64 acc[HH][2];
    #pragma unroll
    for (int h = 0; h < HH; h++) { acc[h][0] = 0ull; acc[h][1] = 0ull; }

    const int l0 = tid, l1 = tid + 256;

    #pragma unroll 1
    for (int c = 0; c < NCH; c++) {
        cpa_wait1();
        __syncthreads();                          // buf[c&1] fully landed

        const float* fb = feat[c & 1];
        const float* wb = Wb + (c & 1) * (HH * KC);

        const ulonglong2 A0 = *(const ulonglong2*)(fb + l0 * FS + 0);
        const ulonglong2 A1 = *(const ulonglong2*)(fb + l0 * FS + 4);
        const ulonglong2 A2 = *(const ulonglong2*)(fb + l0 * FS + 8);
        const ulonglong2 A3 = *(const ulonglong2*)(fb + l0 * FS + 12);
        const ulonglong2 B0 = *(const ulonglong2*)(fb + l1 * FS + 0);
        const ulonglong2 B1 = *(const ulonglong2*)(fb + l1 * FS + 4);
        const ulonglong2 B2 = *(const ulonglong2*)(fb + l1 * FS + 8);
        const ulonglong2 B3 = *(const ulonglong2*)(fb + l1 * FS + 12);

        #pragma unroll
        for (int h = 0; h < HH; h++) {
            const ulonglong2 W0 = *(const ulonglong2*)(wb + h * KC + 0);
            const ulonglong2 W1 = *(const ulonglong2*)(wb + h * KC + 4);
            const ulonglong2 W2 = *(const ulonglong2*)(wb + h * KC + 8);
            const ulonglong2 W3 = *(const ulonglong2*)(wb + h * KC + 12);
            u64 a = acc[h][0], bb2 = acc[h][1];
            a   = ffma2(A0.x, W0.x, a);  bb2 = ffma2(B0.x, W0.x, bb2);
            a   = ffma2(A0.y, W0.y, a);  bb2 = ffma2(B0.y, W0.y, bb2);
            a   = ffma2(A1.x, W1.x, a);  bb2 = ffma2(B1.x, W1.x, bb2);
            a   = ffma2(A1.y, W1.y, a);  bb2 = ffma2(B1.y, W1.y, bb2);
            a   = ffma2(A2.x, W2.x, a);  bb2 = ffma2(B2.x, W2.x, bb2);
            a   = ffma2(A2.y, W2.y, a);  bb2 = ffma2(B2.y, W2.y, bb2);
            a   = ffma2(A3.x, W3.x, a);  bb2 = ffma2(B3.x, W3.x, bb2);
            a   = ffma2(A3.y, W3.y, a);  bb2 = ffma2(B3.y, W3.y, bb2);
            acc[h][0] = a; acc[h][1] = bb2;
        }
        __syncthreads();                          // done reading buf[c&1]

        // issue chunk c+2 into buf[c&1]
        if (c + 2 < NCH) {
            const int k0 = (c + 2) * KC;
            const uint32_t fb2 = smem_u32 + (uint32_t)(((c & 1) ? F1_OFF : F0_OFF) * 4);
            #pragma unroll
            for (int j = 0; j < 8; j++)
                cpa16(fb2 + dsto[j], prop_embed + rowoff[j] + k0);
            if (tid < 32)
                cpa16(smem_u32 + wdst + (uint32_t)((c & 1) * HH * KC * 4), W_att + wsrc + k0);
        }
        cpa_commit();                             // empty group ok near the end
    }
    __syncthreads();

    // ---- write relu'd logits (no split-k: thread owns both its l's fully)
    #pragma unroll
    for (int h = 0; h < HH; h++) {
        const float bs = b_att[h * RR + rc];
        logit_s[h * LL + l0] = fmaxf(f2sum(acc[h][0]) + bs, 0.f);
        logit_s[h * LL + l1] = fmaxf(f2sum(acc[h][1]) + bs, 0.f);
    }
    __syncthreads();

    // ---- softmax per head: warp w owns head w
    {
        const int wid  = tid >> 5;
        const int lane = tid & 31;
        const int h = wid;
        float x[16];
        float m = 0.f;
        #pragma unroll
        for (int i = 0; i < 16; i++) {
            x[i] = logit_s[h * LL + lane + 32 * i];
            m = fmaxf(m, x[i]);
        }
        #pragma unroll
        for (int off = 16; off > 0; off >>= 1)
            m = fmaxf(m, __shfl_xor_sync(0xffffffffu, m, off));
        float s = 0.f;
        #pragma unroll
        for (int i = 0; i < 16; i++) {
            const float e = __expf(x[i] - m);
            logit_s[h * LL + lane + 32 * i] = e;
            s += e;
        }
        #pragma unroll
        for (int off = 16; off > 0; off >>= 1)
            s += __shfl_xor_sync(0xffffffffu, s, off);
        if (lane == 0) inv_s[h] = 1.f / s;
    }
    __syncthreads();

    // ---- attn_mean: write output + keep in smem for pooling
    for (int l = tid; l < LL; l += 256) {
        float s = 0.f;
        #pragma unroll
        for (int h = 0; h < HH; h++)
            s += logit_s[h * LL + l] * inv_s[h];
        s *= (1.0f / HH);
        attn_s[l] = s;
        out[129 + br * (BB * LL) + b * LL + l] = s;
    }
    __syncthreads();

    // ---- value pooling: 4 l-groups x 64 threads, float4 columns, 12-deep MLP
    {
        const int g = tid >> 6;          // l-group
        const int u = tid & 63;          // f4-column thread
        float4 a0 = {0,0,0,0}, a1 = {0,0,0,0}, a2 = {0,0,0,0};
        const float* vb = val + (size_t)(g * 128) * DD;
        const float* am = attn_s + g * 128;
        #pragma unroll 1
        for (int l = 0; l < 128; l += 4) {
            const float w0 = am[l], w1 = am[l + 1], w2 = am[l + 2], w3 = am[l + 3];
            const float4* r0 = (const float4*)(vb + (size_t)l * DD);
            const float4* r1 = (const float4*)(vb + (size_t)(l + 1) * DD);
            const float4* r2 = (const float4*)(vb + (size_t)(l + 2) * DD);
            const float4* r3 = (const float4*)(vb + (size_t)(l + 3) * DD);
            const float4 p0 = __ldcs(r0 + u);
            const float4 p1 = __ldcs(r0 + u + 64);
            const float4 p2 = __ldcs(r0 + u + 128);
            const float4 q0 = __ldcs(r1 + u);
            const float4 q1 = __ldcs(r1 + u + 64);
            const float4 q2 = __ldcs(r1 + u + 128);
            const float4 s0 = __ldcs(r2 + u);
            const float4 s1 = __ldcs(r2 + u + 64);
            const float4 s2 = __ldcs(r2 + u + 128);
            const float4 t0 = __ldcs(r3 + u);
            const float4 t1 = __ldcs(r3 + u + 64);
            const float4 t2 = __ldcs(r3 + u + 128);
            a0.x += w0*p0.x + w1*q0.x + w2*s0.x + w3*t0.x;
            a0.y += w0*p0.y + w1*q0.y + w2*s0.y + w3*t0.y;
            a0.z += w0*p0.z + w1*q0.z + w2*s0.z + w3*t0.z;
            a0.w += w0*p0.w + w1*q0.w + w2*s0.w + w3*t0.w;
            a1.x += w0*p1.x + w1*q1.x + w2*s1.x + w3*t1.x;
            a1.y += w0*p1.y + w1*q1.y + w2*s1.y + w3*t1.y;
            a1.z += w0*p1.z + w1*q1.z + w2*s1.z + w3*t1.z;
            a1.w += w0*p1.w + w1*q1.w + w2*s1.w + w3*t1.w;
            a2.x += w0*p2.x + w1*q2.x + w2*s2.x + w3*t2.x;
            a2.y += w0*p2.y + w1*q2.y + w2*s2.y + w3*t2.y;
            a2.z += w0*p2.z + w1*q2.z + w2*s2.z + w3*t2.z;
            a2.w += w0*p2.w + w1*q2.w + w2*s2.w + w3*t2.w;
        }
        __syncthreads();                 // logit_s dead -> red usable
        float4* rd = (float4*)red;
        rd[g * 192 + u]       = a0;
        rd[g * 192 + u + 64]  = a1;
        rd[g * 192 + u + 128] = a2;
    }
    __syncthreads();
    if (tid < 192) {
        const float4* rd = (const float4*)red;
        float4 s = rd[tid];
        #pragma unroll
        for (int g = 1; g < 4; g++) {
            const float4 t = rd[g * 192 + tid];
            s.x += t.x; s.y += t.y; s.z += t.z; s.w += t.w;
        }
        ((float4*)(g_cat + (size_t)b * (2 * DD) + br * DD))[tid] = s;
    }
}

// one block per b: score[b] = dot(cat[b], W1[rc_b]) + b1[rc_b]
__global__ __launch_bounds__(256)
void k_score(const float* __restrict__ W1,
             const float* __restrict__ b1,
             const int*   __restrict__ rc_ids,
             float*       __restrict__ out)
{
    __shared__ float red[8];
    const int b    = blockIdx.x;
    const int tid  = threadIdx.x;
    const int lane = tid & 31;
    const int wid  = tid >> 5;
    const int rc   = rc_ids[b];

    const float* cat = g_cat + (size_t)b * (2 * DD);
    const float* w   = W1 + (size_t)rc * (2 * DD);

    float s;
    {
        const float4 c0 = *(const float4*)(cat + tid * 4);
        const float4 w0 = *(const float4*)(w   + tid * 4);
        s = c0.x*w0.x + c0.y*w0.y + c0.z*w0.z + c0.w*w0.w;
        if (tid < 128) {
            const float4 c1 = *(const float4*)(cat + (tid + 256) * 4);
            const float4 w1 = *(const float4*)(w   + (tid + 256) * 4);
            s += c1.x*w1.x + c1.y*w1.y + c1.z*w1.z + c1.w*w1.w;
        }
    }
    #pragma unroll
    for (int off = 16; off > 0; off >>= 1)
        s += __shfl_xor_sync(0xffffffffu, s, off);
    if (lane == 0) red[wid] = s;
    __syncthreads();
    if (tid == 0) {
        float t = red[0];
        #pragma unroll
        for (int i = 1; i < 8; i++) t += red[i];
        out[b] = t + b1[rc];
    }
}

__global__ void k_loss(float* __restrict__ out)
{
    const int lane = threadIdx.x;   // 32 threads
    float s = 0.f;
    #pragma unroll
    for (int i = 0; i < 2; i++) {
        const int p = lane + 32 * i;
        s += fmaxf(1.0f - (out[p] - out[p + BB / 2]), 0.f);
    }
    #pragma unroll
    for (int off = 16; off > 0; off >>= 1)
        s += __shfl_xor_sync(0xffffffffu, s, off);
    if (lane == 0) out[BB] = s * (1.0f / (BB / 2));
}

extern "C" void kernel_launch(void* const* d_in, const int* in_sizes, int n_in,
                              void* d_out, int out_size)
{
    const float* head_value = (const float*)d_in[0];
    const float* tail_value = (const float*)d_in[1];
    const float* prop_embed = (const float*)d_in[2];
    const float* W_att      = (const float*)d_in[3];
    const float* b_att      = (const float*)d_in[4];
    const float* W1         = (const float*)d_in[5];
    const float* b1         = (const float*)d_in[6];
    const int*   head_ids   = (const int*)d_in[7];
    const int*   tail_ids   = (const int*)d_in[8];
    const int*   rc_ids     = (const int*)d_in[9];
    float* out = (float*)d_out;

    const int smem_bytes = SMEM_FLOATS * 4;
    cudaFuncSetAttribute(k_pool, cudaFuncAttributeMaxDynamicSharedMemorySize, smem_bytes);

    k_pool<<<2 * BB, 256, smem_bytes>>>(head_value, tail_value, prop_embed,
                                        W_att, b_att, head_ids, tail_ids, rc_ids, out);
    k_score<<<BB, 256>>>(W1, b1, rc_ids, out);
    k_loss<<<1, 32>>>(out);
}